// round 1
// baseline (speedup 1.0000x reference)
#include <cuda_runtime.h>

#define PI_F 3.14159265358979323846f

// ---------------------------------------------------------------------------
// 1-qubit complex 2x2 gate apply on 16-amplitude state held in registers.
// ST = stride of the target qubit (8 >> qubit). Fully unrolled, constant idx.
// g0 = (g00re, g00im, g01re, g01im), g1 = (g10re, g10im, g11re, g11im)
// ---------------------------------------------------------------------------
template <int ST>
__device__ __forceinline__ void apply1q(float* sr, float* si,
                                        const float4 g0, const float4 g1) {
#pragma unroll
    for (int m = 0; m < 8; ++m) {
        const int i0 = ((m & ~(ST - 1)) << 1) | (m & (ST - 1));
        const int i1 = i0 + ST;
        const float ar = sr[i0], ai = si[i0];
        const float br = sr[i1], bi = si[i1];
        sr[i0] = g0.x * ar - g0.y * ai + g0.z * br - g0.w * bi;
        si[i0] = g0.x * ai + g0.y * ar + g0.z * bi + g0.w * br;
        sr[i1] = g1.x * ar - g1.y * ai + g1.z * br - g1.w * bi;
        si[i1] = g1.x * ai + g1.y * ar + g1.z * bi + g1.w * br;
    }
}

// CNOT: for every basis index with control bit set and target bit clear,
// swap with (idx | target_mask). Pure compile-time register permutation.
template <int CM, int TM>
__device__ __forceinline__ void cnot(float* sr, float* si) {
#pragma unroll
    for (int i = 0; i < 16; ++i) {
        if ((i & CM) && !(i & TM)) {
            const int j = i | TM;
            float t;
            t = sr[i]; sr[i] = sr[j]; sr[j] = t;
            t = si[i]; si[i] = si[j]; si[j] = t;
        }
    }
}

// One circuit layer: 4 Rot gates (qubits 0..3) then ring of CNOTs (w, (w+R)%4).
// Qubit w has bit position (3-w) -> mask (8 >> w).
template <int R>
__device__ __forceinline__ void do_layer(float* sr, float* si,
                                         const float4 (*g)[2]) {
    apply1q<8>(sr, si, g[0][0], g[0][1]);
    apply1q<4>(sr, si, g[1][0], g[1][1]);
    apply1q<2>(sr, si, g[2][0], g[2][1]);
    apply1q<1>(sr, si, g[3][0], g[3][1]);
    cnot<(8 >> 0), (8 >> ((0 + R) % 4))>(sr, si);
    cnot<(8 >> 1), (8 >> ((1 + R) % 4))>(sr, si);
    cnot<(8 >> 2), (8 >> ((2 + R) % 4))>(sr, si);
    cnot<(8 >> 3), (8 >> ((3 + R) % 4))>(sr, si);
}

__global__ __launch_bounds__(64) void vqc_kernel(
    const float* __restrict__ x,        // [B, 512]
    const float* __restrict__ W_pre,    // [4, 512]
    const float* __restrict__ b_pre,    // [4]
    const float* __restrict__ q_weights,// [6, 4, 3]
    const float* __restrict__ W_post,   // [10, 4]
    const float* __restrict__ b_post,   // [10]
    float* __restrict__ out,            // [B, 10]
    int B)
{
    __shared__ float4 g_sh[24][2];      // 24 Rot gates, 8 floats each
    __shared__ float wpost_sh[40];
    __shared__ float bpost_sh[10];

    const int tid  = threadIdx.x;
    const int lane = tid & 31;
    const int warp = tid >> 5;
    const int rowBase = blockIdx.x * 64 + warp * 32;

    // ---- Precompute batch-independent Rot gates into smem (threads 0..23) ----
    if (tid < 24) {
        const float phi = q_weights[tid * 3 + 0];
        const float th  = q_weights[tid * 3 + 1];
        const float om  = q_weights[tid * 3 + 2];
        float c, s, cp, sp, cm, sm;
        sincosf(0.5f * th, &s, &c);
        sincosf(0.5f * (phi + om), &sp, &cp);
        sincosf(0.5f * (phi - om), &sm, &cm);
        // ep = exp(-0.5i(phi+om)) = (cp, -sp); em = (cm, -sm)
        // g00 = ep*c, g01 = -conj(em)*s, g10 = em*s, g11 = conj(ep)*c
        g_sh[tid][0] = make_float4(cp * c, -sp * c, -cm * s, -sm * s);
        g_sh[tid][1] = make_float4(cm * s, -sm * s,  cp * c,  sp * c);
    }
    for (int i = tid; i < 50; i += 64) {
        if (i < 40) wpost_sh[i] = W_post[i];
        else        bpost_sh[i - 40] = b_post[i - 40];
    }

    // ---- Phase 1: warp-cooperative GEMV (coalesced x reads) ----
    // W_pre resident in registers: wv[it][w] covers k = it*128 + lane*4 .. +3
    float4 wv[4][4];
#pragma unroll
    for (int it = 0; it < 4; ++it)
#pragma unroll
        for (int w = 0; w < 4; ++w)
            wv[it][w] = *reinterpret_cast<const float4*>(
                W_pre + w * 512 + it * 128 + lane * 4);

    float p0 = 0.f, p1 = 0.f, p2 = 0.f, p3 = 0.f;  // this thread's row sums

    for (int r = 0; r < 32; ++r) {
        int row = rowBase + r;
        if (row >= B) row = B - 1;  // safe clamp (B divisible by 64 normally)
        const float4* xr =
            reinterpret_cast<const float4*>(x + (long)row * 512);
        float a0 = 0.f, a1 = 0.f, a2 = 0.f, a3 = 0.f;
#pragma unroll
        for (int it = 0; it < 4; ++it) {
            const float4 xv = xr[it * 32 + lane];
            a0 = fmaf(xv.x, wv[it][0].x, fmaf(xv.y, wv[it][0].y,
                 fmaf(xv.z, wv[it][0].z, fmaf(xv.w, wv[it][0].w, a0))));
            a1 = fmaf(xv.x, wv[it][1].x, fmaf(xv.y, wv[it][1].y,
                 fmaf(xv.z, wv[it][1].z, fmaf(xv.w, wv[it][1].w, a1))));
            a2 = fmaf(xv.x, wv[it][2].x, fmaf(xv.y, wv[it][2].y,
                 fmaf(xv.z, wv[it][2].z, fmaf(xv.w, wv[it][2].w, a2))));
            a3 = fmaf(xv.x, wv[it][3].x, fmaf(xv.y, wv[it][3].y,
                 fmaf(xv.z, wv[it][3].z, fmaf(xv.w, wv[it][3].w, a3))));
        }
#pragma unroll
        for (int off = 16; off > 0; off >>= 1) {
            a0 += __shfl_xor_sync(0xffffffffu, a0, off);
            a1 += __shfl_xor_sync(0xffffffffu, a1, off);
            a2 += __shfl_xor_sync(0xffffffffu, a2, off);
            a3 += __shfl_xor_sync(0xffffffffu, a3, off);
        }
        if (lane == r) { p0 = a0; p1 = a1; p2 = a2; p3 = a3; }
    }

    __syncthreads();  // gates + post weights ready in smem

    // ---- Phase 2: thread-per-row quantum circuit in registers ----
    const int row = rowBase + lane;   // == blockIdx.x*64 + tid
    if (row >= B) return;

    float cw[4], sw[4];
    {
        const float bp0 = __ldg(b_pre + 0), bp1 = __ldg(b_pre + 1);
        const float bp2 = __ldg(b_pre + 2), bp3 = __ldg(b_pre + 3);
        float ang;
        ang = tanhf(p0 + bp0) * PI_F; sincosf(0.5f * ang, &sw[0], &cw[0]);
        ang = tanhf(p1 + bp1) * PI_F; sincosf(0.5f * ang, &sw[1], &cw[1]);
        ang = tanhf(p2 + bp2) * PI_F; sincosf(0.5f * ang, &sw[2], &cw[2]);
        ang = tanhf(p3 + bp3) * PI_F; sincosf(0.5f * ang, &sw[3], &cw[3]);
    }

    // Initial state after the RY layer is the (real) product state.
    float sr[16], si[16];
#pragma unroll
    for (int i = 0; i < 16; ++i) {
        sr[i] = ((i & 8) ? sw[0] : cw[0]) * ((i & 4) ? sw[1] : cw[1]) *
                ((i & 2) ? sw[2] : cw[2]) * ((i & 1) ? sw[3] : cw[3]);
        si[i] = 0.f;
    }

    // 6 layers; r pattern is (1,2,3) repeated -> roll x2 to halve I-footprint.
#pragma unroll 1
    for (int h = 0; h < 2; ++h) {
        const float4 (*gb)[2] = &g_sh[h * 12];
        do_layer<1>(sr, si, gb + 0);
        do_layer<2>(sr, si, gb + 4);
        do_layer<3>(sr, si, gb + 8);
    }

    // ---- Z expectations per qubit ----
    float e0 = 0.f, e1 = 0.f, e2 = 0.f, e3 = 0.f;
#pragma unroll
    for (int i = 0; i < 16; ++i) {
        const float pr = sr[i] * sr[i] + si[i] * si[i];
        e0 += (i & 8) ? -pr : pr;
        e1 += (i & 4) ? -pr : pr;
        e2 += (i & 2) ? -pr : pr;
        e3 += (i & 1) ? -pr : pr;
    }

    // ---- Post linear 4 -> 10, vectorized float2 stores (40B row, 8B aligned) ----
    float o[10];
#pragma unroll
    for (int c = 0; c < 10; ++c) {
        o[c] = bpost_sh[c]
             + e0 * wpost_sh[c * 4 + 0] + e1 * wpost_sh[c * 4 + 1]
             + e2 * wpost_sh[c * 4 + 2] + e3 * wpost_sh[c * 4 + 3];
    }
    float2* op = reinterpret_cast<float2*>(out + (long)row * 10);
#pragma unroll
    for (int c = 0; c < 5; ++c) op[c] = make_float2(o[2 * c], o[2 * c + 1]);
}

extern "C" void kernel_launch(void* const* d_in, const int* in_sizes, int n_in,
                              void* d_out, int out_size) {
    const float* x    = (const float*)d_in[0];
    const float* Wpre = (const float*)d_in[1];
    const float* bpre = (const float*)d_in[2];
    const float* qw   = (const float*)d_in[3];
    const float* Wpo  = (const float*)d_in[4];
    const float* bpo  = (const float*)d_in[5];
    float* out = (float*)d_out;

    const int B = in_sizes[0] / 512;
    const int grid = (B + 63) / 64;
    vqc_kernel<<<grid, 64>>>(x, Wpre, bpre, qw, Wpo, bpo, out, B);
}